// round 2
// baseline (speedup 1.0000x reference)
#include <cuda_runtime.h>
#include <math.h>

#define NN 100000
#define D 256
#define DOUT 64
#define EMAX 3200000
#define SCAN_B 1024
#define NSCAN ((NN + SCAN_B - 1) / SCAN_B)

// ---------------- scratch (device globals; no allocation allowed) ----------
__device__ __align__(16) float g_h0[(size_t)NN * D];   // ~102 MB
__device__ __align__(16) float g_h1[(size_t)NN * D];   // ~102 MB
__device__ __align__(16) float g_w2[D * D];
__device__ float g_b2[D];
__device__ float g_sum[D], g_sumsq[D], g_a[D], g_bv[D];
__device__ int g_cnt[NN], g_cur[NN];
__device__ int g_off[NN + 1];
__device__ int g_bsum[NSCAN], g_bpre[NSCAN];
__device__ int g_ecol[EMAX];
__device__ float g_eval[EMAX];

// ---------------- zero scratch ---------------------------------------------
__global__ void k_zero() {
    int i = blockIdx.x * blockDim.x + threadIdx.x;
    if (i < NN) { g_cnt[i] = 0; g_cur[i] = 0; }
    if (i < D)  { g_sum[i] = 0.f; g_sumsq[i] = 0.f; }
}

// ---------------- BatchNorm stats ------------------------------------------
__global__ void k_bnsum(const float* __restrict__ x) {
    int c = threadIdx.x;                 // feature column 0..255
    int rows_per = (NN + gridDim.x - 1) / gridDim.x;
    int r0 = blockIdx.x * rows_per;
    int r1 = min(r0 + rows_per, NN);
    float s = 0.f, s2 = 0.f;
    for (int r = r0; r < r1; r++) {
        float v = x[(size_t)r * D + c];
        s += v; s2 += v * v;
    }
    atomicAdd(&g_sum[c], s);
    atomicAdd(&g_sumsq[c], s2);
}

__global__ void k_bnfin(const float* __restrict__ gamma, const float* __restrict__ beta) {
    int c = threadIdx.x;
    float mean = g_sum[c] * (1.f / NN);
    float var  = g_sumsq[c] * (1.f / NN) - mean * mean;
    float a = gamma[c] * rsqrtf(var + 1e-5f);
    g_a[c] = a;
    g_bv[c] = beta[c] - mean * a;
}

// fold BN into GEMM1 weights: w2[k][j] = a[k] * w_in[k][j]
__global__ void k_prepw(const float* __restrict__ w_in) {
    int k = blockIdx.x, j = threadIdx.x;
    g_w2[k * D + j] = g_a[k] * w_in[k * D + j];
}

// b2[j] = sum_k bv[k] * w_in[k][j] + b_in[j]
__global__ void k_prepb(const float* __restrict__ w_in, const float* __restrict__ b_in) {
    int j = threadIdx.x;
    float s = b_in[j];
    for (int k = 0; k < D; k++) s += g_bv[k] * w_in[k * D + j];
    g_b2[j] = s;
}

// ---------------- CSR build -------------------------------------------------
__global__ void k_hist(const int* __restrict__ rows, int E) {
    int i = blockIdx.x * blockDim.x + threadIdx.x;
    if (i < E) atomicAdd(&g_cnt[rows[i]], 1);
}

__global__ void k_scan1() {
    __shared__ int s[SCAN_B];
    int t = threadIdx.x;
    int i = blockIdx.x * SCAN_B + t;
    int v = (i < NN) ? g_cnt[i] : 0;
    s[t] = v;
    __syncthreads();
    for (int o = 1; o < SCAN_B; o <<= 1) {
        int add = (t >= o) ? s[t - o] : 0;
        __syncthreads();
        s[t] += add;
        __syncthreads();
    }
    if (i < NN) g_off[i + 1] = s[t];
    if (t == SCAN_B - 1) g_bsum[blockIdx.x] = s[t];
}

__global__ void k_scan2(int nb) {
    if (threadIdx.x == 0) {
        int run = 0;
        for (int b = 0; b < nb; b++) { g_bpre[b] = run; run += g_bsum[b]; }
    }
}

__global__ void k_scan3() {
    int i = blockIdx.x * blockDim.x + threadIdx.x;
    if (i == 0) g_off[0] = 0;
    if (i < NN) g_off[i + 1] += g_bpre[i >> 10];
}

__global__ void k_scatter(const int* __restrict__ rows, const int* __restrict__ cols,
                          const float* __restrict__ vals, int E) {
    int i = blockIdx.x * blockDim.x + threadIdx.x;
    if (i >= E) return;
    int r = rows[i];
    int p = g_off[r] + atomicAdd(&g_cur[r], 1);
    g_ecol[p] = cols[i];
    g_eval[p] = vals[i];
}

// ---------------- SpMM (CSR gather, 64 threads/row, float4 lanes) -----------
__global__ void __launch_bounds__(256) k_spmm(int dir) {
    const float4* __restrict__ xin = dir ? (const float4*)g_h1 : (const float4*)g_h0;
    float4* __restrict__ yout      = dir ? (float4*)g_h0 : (float4*)g_h1;
    int r = blockIdx.x * 4 + (threadIdx.x >> 6);
    int lane = threadIdx.x & 63;               // 64 lanes * float4 = 256 features
    int e = g_off[r], e1 = g_off[r + 1];
    float4 acc = make_float4(0.f, 0.f, 0.f, 0.f);
    for (; e + 4 <= e1; e += 4) {
        int c0 = g_ecol[e], c1 = g_ecol[e + 1], c2 = g_ecol[e + 2], c3 = g_ecol[e + 3];
        float v0 = g_eval[e], v1 = g_eval[e + 1], v2 = g_eval[e + 2], v3 = g_eval[e + 3];
        float4 x0 = xin[(size_t)c0 * 64 + lane];
        float4 x1 = xin[(size_t)c1 * 64 + lane];
        float4 x2 = xin[(size_t)c2 * 64 + lane];
        float4 x3 = xin[(size_t)c3 * 64 + lane];
        acc.x = fmaf(v0, x0.x, acc.x); acc.y = fmaf(v0, x0.y, acc.y);
        acc.z = fmaf(v0, x0.z, acc.z); acc.w = fmaf(v0, x0.w, acc.w);
        acc.x = fmaf(v1, x1.x, acc.x); acc.y = fmaf(v1, x1.y, acc.y);
        acc.z = fmaf(v1, x1.z, acc.z); acc.w = fmaf(v1, x1.w, acc.w);
        acc.x = fmaf(v2, x2.x, acc.x); acc.y = fmaf(v2, x2.y, acc.y);
        acc.z = fmaf(v2, x2.z, acc.z); acc.w = fmaf(v2, x2.w, acc.w);
        acc.x = fmaf(v3, x3.x, acc.x); acc.y = fmaf(v3, x3.y, acc.y);
        acc.z = fmaf(v3, x3.z, acc.z); acc.w = fmaf(v3, x3.w, acc.w);
    }
    for (; e < e1; e++) {
        int c = g_ecol[e]; float v = g_eval[e];
        float4 xv = xin[(size_t)c * 64 + lane];
        acc.x = fmaf(v, xv.x, acc.x); acc.y = fmaf(v, xv.y, acc.y);
        acc.z = fmaf(v, xv.z, acc.z); acc.w = fmaf(v, xv.w, acc.w);
    }
    yout[(size_t)r * 64 + lane] = acc;
}

// ---------------- tiled fp32 GEMM: C = act(A[M,256] @ B[256,N] + bias) ------
template <bool TANH>
__global__ void __launch_bounds__(256) k_gemm(const float* __restrict__ A,
                                              const float* __restrict__ B,
                                              const float* __restrict__ bias,
                                              float* __restrict__ C,
                                              int M, int N) {
    __shared__ float As[16][128];
    __shared__ float Bs[16][64];
    const int tid = threadIdx.x;
    const int tx = tid & 15, ty = tid >> 4;
    const int bm = blockIdx.x * 128;
    const int bn = blockIdx.y * 64;
    float acc[8][4];
#pragma unroll
    for (int i = 0; i < 8; i++)
#pragma unroll
        for (int j = 0; j < 4; j++) acc[i][j] = 0.f;

    for (int k0 = 0; k0 < 256; k0 += 16) {
#pragma unroll
        for (int q = 0; q < 2; q++) {
            int idx = tid * 2 + q;
            int row = idx >> 2, cg = idx & 3;
            int gr = bm + row;
            float4 v = make_float4(0.f, 0.f, 0.f, 0.f);
            if (gr < M) v = *(const float4*)(A + (size_t)gr * 256 + k0 + cg * 4);
            As[cg * 4 + 0][row] = v.x;
            As[cg * 4 + 1][row] = v.y;
            As[cg * 4 + 2][row] = v.z;
            As[cg * 4 + 3][row] = v.w;
        }
        {
            int row = tid >> 4, c4 = tid & 15;
            *(float4*)&Bs[row][c4 * 4] =
                *(const float4*)(B + (size_t)(k0 + row) * N + bn + c4 * 4);
        }
        __syncthreads();
#pragma unroll
        for (int k = 0; k < 16; k++) {
            float4 a0 = *(const float4*)&As[k][ty * 8];
            float4 a1 = *(const float4*)&As[k][ty * 8 + 4];
            float4 b0 = *(const float4*)&Bs[k][tx * 4];
            float av[8] = {a0.x, a0.y, a0.z, a0.w, a1.x, a1.y, a1.z, a1.w};
            float bv4[4] = {b0.x, b0.y, b0.z, b0.w};
#pragma unroll
            for (int i = 0; i < 8; i++)
#pragma unroll
                for (int j = 0; j < 4; j++)
                    acc[i][j] = fmaf(av[i], bv4[j], acc[i][j]);
        }
        __syncthreads();
    }

    float4 bb = *(const float4*)(bias + bn + tx * 4);
#pragma unroll
    for (int i = 0; i < 8; i++) {
        int gr = bm + ty * 8 + i;
        if (gr < M) {
            float4 o;
            o.x = acc[i][0] + bb.x;
            o.y = acc[i][1] + bb.y;
            o.z = acc[i][2] + bb.z;
            o.w = acc[i][3] + bb.w;
            if (TANH) {
                o.x = tanhf(o.x); o.y = tanhf(o.y);
                o.z = tanhf(o.z); o.w = tanhf(o.w);
            }
            *(float4*)(C + (size_t)gr * N + bn + tx * 4) = o;
        }
    }
}

// ---------------- launch -----------------------------------------------------
extern "C" void kernel_launch(void* const* d_in, const int* in_sizes, int n_in,
                              void* d_out, int out_size) {
    const float* x      = (const float*)d_in[0];
    const int*   erows  = (const int*)d_in[1];
    const int*   ecols  = (const int*)d_in[2];
    const float* evals  = (const float*)d_in[3];
    const float* gamma  = (const float*)d_in[4];
    const float* beta   = (const float*)d_in[5];
    const float* w_in   = (const float*)d_in[6];
    const float* b_in   = (const float*)d_in[7];
    const float* w_conv = (const float*)d_in[8];
    const float* b_conv = (const float*)d_in[9];
    const float* w_out  = (const float*)d_in[10];
    const float* b_out  = (const float*)d_in[11];
    const int E = in_sizes[1];
    float* out = (float*)d_out;

    float *p_h0, *p_h1, *p_w2, *p_b2;
    cudaGetSymbolAddress((void**)&p_h0, g_h0);
    cudaGetSymbolAddress((void**)&p_h1, g_h1);
    cudaGetSymbolAddress((void**)&p_w2, g_w2);
    cudaGetSymbolAddress((void**)&p_b2, g_b2);

    // BN stats + folded weights
    k_zero<<<(NN + 255) / 256, 256>>>();
    k_bnsum<<<512, 256>>>(x);
    k_bnfin<<<1, 256>>>(gamma, beta);
    k_prepw<<<256, 256>>>(w_in);
    k_prepb<<<1, 256>>>(w_in, b_in);

    // CSR build
    k_hist<<<(E + 255) / 256, 256>>>(erows, E);
    k_scan1<<<NSCAN, SCAN_B>>>();
    k_scan2<<<1, 32>>>(NSCAN);
    k_scan3<<<(NN + 255) / 256, 256>>>();
    k_scatter<<<(E + 255) / 256, 256>>>(erows, ecols, evals, E);

    // GEMM1 (BN folded) + tanh -> h0
    dim3 g1((NN + 127) / 128, 4);
    k_gemm<true><<<g1, 256>>>(x, p_w2, p_b2, p_h0, NN, 256);

    // 4 SpMM hops (ping-pong h0 <-> h1), end in h0
    k_spmm<<<NN / 4, 256>>>(0);
    k_spmm<<<NN / 4, 256>>>(1);
    k_spmm<<<NN / 4, 256>>>(0);
    k_spmm<<<NN / 4, 256>>>(1);

    // GEMM2 + tanh -> h1
    k_gemm<true><<<g1, 256>>>(p_h0, w_conv, b_conv, p_h1, NN, 256);

    // GEMM3 (logits) -> d_out
    dim3 g3((NN + 127) / 128, 1);
    k_gemm<false><<<g3, 256>>>(p_h1, w_out, b_out, out, NN, 64);
}